// round 17
// baseline (speedup 1.0000x reference)
#include <cuda_runtime.h>
#include <cuda_bf16.h>

// Problem constants (fixed by the reference: B=4, S=2048, D=2048, K=4)
#define N_ROWS       8192    // B*S
#define N_COLS4      512     // float4 per row (D/4)
#define TPB          256     // half-row per block
#define ROWS_PER_BLK 8       // two 4-row waves
#define N_ROWGROUPS  (N_ROWS / ROWS_PER_BLK)   // 1024
#define GRID         (2 * N_ROWGROUPS)         // 2048
#define WAVE         4

// Scratch (__device__ globals: the sanctioned no-allocation pattern).
__device__ float4 g_wt[2048];   // g_wt[j*512 + c] = w4[4c + j], j in 0..3
__device__ float4 g_coef[6];    // {A k0..3},{B},{C},{D},{E},{F} packed per float4

__device__ __forceinline__ float fast_ex2(float a) {
    float r;
    asm("ex2.approx.ftz.f32 %0, %1;" : "=f"(r) : "f"(a));
    return r;
}

// Pre-pass: coalesced-write weight transpose + coefficient folding (packed
// as float4 so the main kernel reads 6 broadcast LDG.128 instead of 24 LDG.32).
__global__ void prep_kernel(const float4* __restrict__ w4,
                            const float*  __restrict__ means,
                            const float*  __restrict__ icov)
{
    const int i = blockIdx.x * blockDim.x + threadIdx.x;   // 0..2047
    g_wt[i] = w4[4 * (i & 511) + (i >> 9)];

    if (i == 0) {
        // log2(pdf_k) = A*x^2 + B*x*y + C*y^2 + D*x + E*y + F  (-0.5*log2e folded)
        const float L2E = 1.4426950408889634f;
        float A[4], B[4], C[4], D[4], E[4], F[4];
#pragma unroll
        for (int k = 0; k < 4; k++) {
            const float m0 = means[2 * k + 0];
            const float m1 = means[2 * k + 1];
            const float a  = icov[4 * k + 0];
            const float b  = 0.5f * (icov[4 * k + 1] + icov[4 * k + 2]);
            const float cc = icov[4 * k + 3];
            const float C0 = -0.5f * L2E * a;
            const float C1 = -L2E * b;
            const float C2 = -0.5f * L2E * cc;
            A[k] = C0;
            B[k] = C1;
            C[k] = C2;
            D[k] = -(2.0f * C0 * m0 + C1 * m1);
            E[k] = -(C1 * m0 + 2.0f * C2 * m1);
            F[k] = C0 * m0 * m0 + C1 * m0 * m1 + C2 * m1 * m1;
        }
        g_coef[0] = make_float4(A[0], A[1], A[2], A[3]);
        g_coef[1] = make_float4(B[0], B[1], B[2], B[3]);
        g_coef[2] = make_float4(C[0], C[1], C[2], C[3]);
        g_coef[3] = make_float4(D[0], D[1], D[2], D[3]);
        g_coef[4] = make_float4(E[0], E[1], E[2], E[3]);
        g_coef[5] = make_float4(F[0], F[1], F[2], F[3]);
    }
}

__global__ void __launch_bounds__(TPB)
gmm_act_kernel(const float4* __restrict__ xin,
               float4* __restrict__ out)
{
    const int tid = threadIdx.x;
    const int c   = ((blockIdx.x & 1) << 8) + tid;   // float4 column 0..511
    const int rb  = blockIdx.x >> 1;                 // row-group 0..1023

    // Prefolded coefficients: 6 broadcast LDG.128.
    const float4 vA = g_coef[0], vB = g_coef[1], vC = g_coef[2];
    const float4 vD = g_coef[3], vE = g_coef[4], vF = g_coef[5];
    const float cA[4] = {vA.x, vA.y, vA.z, vA.w};
    const float cB[4] = {vB.x, vB.y, vB.z, vB.w};
    const float cC[4] = {vC.x, vC.y, vC.z, vC.w};
    const float cD[4] = {vD.x, vD.y, vD.z, vD.w};
    const float cE[4] = {vE.x, vE.y, vE.z, vE.w};
    const float cF[4] = {vF.x, vF.y, vF.z, vF.w};

    // Weights for this thread's two d-pairs (d0 = 2c, d1 = 2c+1), from the
    // transposed buffer: 4 fully-coalesced LDG.128 — amortized over 8 rows.
    const float4 wa = g_wt[       c];   // d0: k0c0 k0c1 k1c0 k1c1
    const float4 wb = g_wt[ 512 + c];   // d0: k2c0 k2c1 k3c0 k3c1
    const float4 wc = g_wt[1024 + c];   // d1: k0c0 k0c1 k1c0 k1c1
    const float4 wd = g_wt[1536 + c];   // d1: k2c0 k2c1 k3c0 k3c1
    const float w0c0[4] = {wa.x, wa.z, wb.x, wb.z};
    const float w0c1[4] = {wa.y, wa.w, wb.y, wb.w};
    const float w1c0[4] = {wc.x, wc.z, wd.x, wd.z};
    const float w1c1[4] = {wc.y, wc.w, wd.y, wd.w};

    // Two sequential waves of 4 rows: front-batch 4 loads (MLP=4), compute,
    // repeat. One wave of v[] alive at a time keeps regs ~R15-level.
#pragma unroll
    for (int wgrp = 0; wgrp < ROWS_PER_BLK / WAVE; wgrp++) {
        float4 v[WAVE];
        int    idx[WAVE];
#pragma unroll
        for (int i = 0; i < WAVE; i++) {
            const int r = rb + (wgrp * WAVE + i) * N_ROWGROUPS;
            idx[i] = r * N_COLS4 + c;
            v[i]   = xin[idx[i]];
        }

#pragma unroll
        for (int i = 0; i < WAVE; i++) {
            const float x0 = v[i].x, y0 = v[i].y;
            const float x1 = v[i].z, y1 = v[i].w;

            float r00 = 0.0f, r01 = 0.0f, r10 = 0.0f, r11 = 0.0f;
#pragma unroll
            for (int k = 0; k < 4; k++) {
                // arg = x*(A*x + (B*y + D)) + ((C*y + E)*y + F), depth 3.
                float t0 = fmaf(cA[k], x0, fmaf(cB[k], y0, cD[k]));
                float t1 = fmaf(cA[k], x1, fmaf(cB[k], y1, cD[k]));
                float u0 = fmaf(fmaf(cC[k], y0, cE[k]), y0, cF[k]);
                float u1 = fmaf(fmaf(cC[k], y1, cE[k]), y1, cF[k]);
                const float p0 = fast_ex2(fmaf(x0, t0, u0));
                const float p1 = fast_ex2(fmaf(x1, t1, u1));
                r00 = fmaf(p0, w0c0[k], r00);
                r01 = fmaf(p0, w0c1[k], r01);
                r10 = fmaf(p1, w1c0[k], r10);
                r11 = fmaf(p1, w1c1[k], r11);
            }

            float4 o;
            o.x = x0 * r00;
            o.y = y0 * r01;
            o.z = x1 * r10;
            o.w = y1 * r11;
            // Streaming store: write-once data must not displace x from L2.
            __stcs(&out[idx[i]], o);
        }
    }
}

extern "C" void kernel_launch(void* const* d_in, const int* in_sizes, int n_in,
                              void* d_out, int out_size)
{
    // Inputs identified by element count: x=16777216, means=8, icov=16, w=8192.
    const float* x     = nullptr;
    const float* means = nullptr;
    const float* icov  = nullptr;
    const float* w     = nullptr;
    for (int i = 0; i < n_in; i++) {
        const int n = in_sizes[i];
        if      (n == 16777216) x     = (const float*)d_in[i];
        else if (n == 8)        means = (const float*)d_in[i];
        else if (n == 16)       icov  = (const float*)d_in[i];
        else if (n == 8192)     w     = (const float*)d_in[i];
    }

    prep_kernel<<<4, 512>>>((const float4*)w, means, icov);
    gmm_act_kernel<<<GRID, TPB>>>((const float4*)x, (float4*)d_out);
}